// round 1
// baseline (speedup 1.0000x reference)
#include <cuda_runtime.h>

// GraphSage 2-layer, fp32 baseline.
// Layer shape (both layers): table[T][128], nodes[B], neigh[B][10], W[128][256]
//   out[b][o] = relu( sum_d self[d]*W[o][d] + agg[d]*W[o][128+d] ),
//   self = table[nodes[b]], agg = mean_k table[neigh[b][k]].

#define DD     128      // feature dim (both layers)
#define KN     10       // sampled neighbors
#define BM     32       // frontier rows per block
#define KT     64       // k-tile width for W
#define WST    68       // padded Wsh row stride (floats)
#define B1_SZ  40960
#define B2_SZ  4096

// layer-1 hidden table scratch (21 MB) — __device__ global per allocation rules
__device__ float g_h1[B1_SZ * DD];

__global__ __launch_bounds__(256, 3)
void sage_layer_kernel(const float* __restrict__ table,   // [T][128]
                       const float* __restrict__ W,       // [128][256] row-major
                       const int*   __restrict__ nodes,   // [B]
                       const int*   __restrict__ neigh,   // [B][10]
                       float*       __restrict__ out,     // [B][128]
                       int B)
{
    extern __shared__ __align__(16) char smem_raw[];
    float* comb = (float*)smem_raw;                 // [BM][2*DD] = 32x256
    float* Wsh  = comb + BM * 2 * DD;               // [128][WST]

    const int tid  = threadIdx.x;
    const int b0   = blockIdx.x * BM;
    const int warp = tid >> 5;
    const int lane = tid & 31;

    // ---------------- Phase 1: gather + mean into comb ----------------
    // warp-per-row; each lane handles one float4 (4 consecutive feature dims)
    #pragma unroll
    for (int r = warp; r < BM; r += 8) {
        const int row = b0 + r;
        if (row < B) {
            const int node = nodes[row];
            float4 v = ((const float4*)table)[(long long)node * 32 + lane];
            ((float4*)(comb + r * 2 * DD))[lane] = v;

            float4 acc = make_float4(0.f, 0.f, 0.f, 0.f);
            #pragma unroll
            for (int k = 0; k < KN; k++) {
                const int idx = neigh[row * KN + k];
                float4 u = ((const float4*)table)[(long long)idx * 32 + lane];
                acc.x += u.x; acc.y += u.y; acc.z += u.z; acc.w += u.w;
            }
            const float s = 1.0f / (float)KN;
            acc.x *= s; acc.y *= s; acc.z *= s; acc.w *= s;
            ((float4*)(comb + r * 2 * DD))[32 + lane] = acc;
        }
    }

    // ---------------- Phase 2: C[32][128] = comb[32][256] @ W^T ----------------
    // thread (ty,tx): ty = tid>>4 (16 row-groups of 2), tx = tid&15 (16 col-groups of 8)
    // micro-tile: 2 rows x 8 cols, cols strided by 16 (col = tx + 16j)
    const int tx = tid & 15;
    const int ty = tid >> 4;

    float acc[2][8];
    #pragma unroll
    for (int i = 0; i < 2; i++)
        #pragma unroll
        for (int j = 0; j < 8; j++) acc[i][j] = 0.f;

    for (int kt = 0; kt < 2 * DD; kt += KT) {
        __syncthreads();   // comb ready (first iter) / previous Wsh tile consumed
        // load W[:, kt:kt+KT] into Wsh[col][k] (col-major over k, stride WST)
        #pragma unroll
        for (int r8 = 0; r8 < 8; r8++) {
            const int rw = (tid >> 4) + r8 * 16;        // 0..127
            const int c4 = (tid & 15);                  // float4 index within tile
            float4 wv = ((const float4*)W)[rw * (2 * DD / 4) + (kt >> 2) + c4];
            *((float4*)(Wsh + rw * WST + c4 * 4)) = wv;
        }
        __syncthreads();

        #pragma unroll
        for (int k0 = 0; k0 < KT; k0 += 4) {
            float4 a4[2];
            #pragma unroll
            for (int i = 0; i < 2; i++)
                a4[i] = *((const float4*)(comb + (ty * 2 + i) * 2 * DD + kt + k0));
            float4 b4[8];
            #pragma unroll
            for (int j = 0; j < 8; j++)
                b4[j] = *((const float4*)(Wsh + (tx + 16 * j) * WST + k0));
            #pragma unroll
            for (int i = 0; i < 2; i++)
                #pragma unroll
                for (int j = 0; j < 8; j++)
                    acc[i][j] += a4[i].x * b4[j].x + a4[i].y * b4[j].y
                               + a4[i].z * b4[j].z + a4[i].w * b4[j].w;
        }
    }

    // ---------------- Epilogue: ReLU + store ----------------
    #pragma unroll
    for (int i = 0; i < 2; i++) {
        const int row = b0 + ty * 2 + i;
        if (row < B) {
            #pragma unroll
            for (int j = 0; j < 8; j++) {
                const int col = tx + 16 * j;
                out[row * DD + col] = fmaxf(acc[i][j], 0.f);
            }
        }
    }
}

extern "C" void kernel_launch(void* const* d_in, const int* in_sizes, int n_in,
                              void* d_out, int out_size)
{
    const float* raw    = (const float*)d_in[0];   // [1e6][128]
    const float* W1     = (const float*)d_in[1];   // [128][256]
    const float* W2     = (const float*)d_in[2];   // [128][256]
    const int*   nodes1 = (const int*)  d_in[3];   // [40960]
    const int*   neigh1 = (const int*)  d_in[4];   // [40960][10]
    const int*   nodes2 = (const int*)  d_in[5];   // [4096]
    const int*   neigh2 = (const int*)  d_in[6];   // [4096][10]
    float*       out    = (float*)d_out;           // [4096][128]

    float* h1 = nullptr;
    cudaGetSymbolAddress((void**)&h1, g_h1);

    const int smem = (BM * 2 * DD + DD * WST) * (int)sizeof(float); // 66,816 B
    static bool attr_done = false;
    if (!attr_done) {
        cudaFuncSetAttribute(sage_layer_kernel,
                             cudaFuncAttributeMaxDynamicSharedMemorySize, smem);
        attr_done = true;
    }

    // Layer 1: table = raw features, B = 40960
    sage_layer_kernel<<<B1_SZ / BM, 256, smem>>>(raw, W1, nodes1, neigh1, h1, B1_SZ);
    // Layer 2: table = h1, B = 4096
    sage_layer_kernel<<<B2_SZ / BM, 256, smem>>>(h1, W2, nodes2, neigh2, out, B2_SZ);
}

// round 2
// speedup vs baseline: 1.4830x; 1.4830x over previous
#include <cuda_runtime.h>
#include <cstdint>

// GraphSage 2-layer.
// Layer 1: tf32 tensor-core (mma.sync m16n8k8), BM=64 rows/block.
// Layer 2: fp32 FFMA, BM=16 rows/block (occupancy fix for small B).

#define DD     128
#define KN     10
#define B1_SZ  40960
#define B2_SZ  4096

#define CPAD   260     // comb row stride (floats), 260%32==4 -> conflict-free frags
#define WPAD   68      // Wsh row stride (floats),  68%32==4  -> conflict-free frags
#define BM1    64      // layer-1 rows per block
#define KT1    64      // layer-1 W k-tile

__device__ float g_h1[B1_SZ * DD];

__device__ __forceinline__ uint32_t f2tf32(float f) {
    uint32_t u;
    asm("cvt.rna.tf32.f32 %0, %1;" : "=r"(u) : "f"(f));
    return u;
}

__device__ __forceinline__ void mma_tf32(float& c0, float& c1, float& c2, float& c3,
                                         uint32_t a0, uint32_t a1, uint32_t a2, uint32_t a3,
                                         uint32_t b0, uint32_t b1) {
    asm volatile(
        "mma.sync.aligned.m16n8k8.row.col.f32.tf32.tf32.f32 "
        "{%0,%1,%2,%3}, {%4,%5,%6,%7}, {%8,%9}, {%0,%1,%2,%3};\n"
        : "+f"(c0), "+f"(c1), "+f"(c2), "+f"(c3)
        : "r"(a0), "r"(a1), "r"(a2), "r"(a3), "r"(b0), "r"(b1));
}

// ---------------------------------------------------------------------------
// Layer-1 kernel: gather+mean (fp32) -> tf32 comb in smem -> tensor-core GEMM
// out[b][o] = relu( sum_k comb[b][k] * W[o][k] ),  comb = [self | mean_neigh]
// ---------------------------------------------------------------------------
__global__ __launch_bounds__(256, 2)
void sage_l1_tf32(const float* __restrict__ table,   // [1e6][128]
                  const float* __restrict__ W,       // [128][256]
                  const int*   __restrict__ nodes,   // [B]
                  const int*   __restrict__ neigh,   // [B][10]
                  float*       __restrict__ out,     // [B][128]
                  int B)
{
    extern __shared__ __align__(16) float smem[];
    float* comb = smem;                      // [BM1][CPAD]
    float* Wsh  = smem + BM1 * CPAD;         // [128][WPAD]

    const int tid  = threadIdx.x;
    const int warp = tid >> 5;
    const int lane = tid & 31;
    const int b0   = blockIdx.x * BM1;

    // ---------- Phase 1: gather + mean, converted to tf32 into comb ----------
    #pragma unroll
    for (int i = 0; i < BM1 / 8; i++) {
        const int r   = warp * (BM1 / 8) + i;
        const int row = b0 + r;
        const int node = nodes[row];
        float4 v = __ldg(((const float4*)table) + (long long)node * 32 + lane);
        uint32_t* cs = (uint32_t*)(comb + r * CPAD);
        cs[lane * 4 + 0] = f2tf32(v.x);
        cs[lane * 4 + 1] = f2tf32(v.y);
        cs[lane * 4 + 2] = f2tf32(v.z);
        cs[lane * 4 + 3] = f2tf32(v.w);

        float4 acc = make_float4(0.f, 0.f, 0.f, 0.f);
        #pragma unroll
        for (int k = 0; k < KN; k++) {
            const int idx = neigh[row * KN + k];
            float4 u = __ldg(((const float4*)table) + (long long)idx * 32 + lane);
            acc.x += u.x; acc.y += u.y; acc.z += u.z; acc.w += u.w;
        }
        const float s = 1.0f / (float)KN;
        cs[DD + lane * 4 + 0] = f2tf32(acc.x * s);
        cs[DD + lane * 4 + 1] = f2tf32(acc.y * s);
        cs[DD + lane * 4 + 2] = f2tf32(acc.z * s);
        cs[DD + lane * 4 + 3] = f2tf32(acc.w * s);
    }

    // ---------- Phase 2: tensor-core GEMM ----------
    // warps: mwarp = warp&3 (16-row tiles), nhalf = warp>>2 (64-col halves)
    const int g     = lane >> 2;      // groupID
    const int tig   = lane & 3;       // thread-in-group
    const int mbase = (warp & 3) * 16;
    const int nbase = (warp >> 2) * 64;

    float acc[8][4];
    #pragma unroll
    for (int nt = 0; nt < 8; nt++)
        #pragma unroll
        for (int j = 0; j < 4; j++) acc[nt][j] = 0.f;

    for (int kt = 0; kt < 2 * DD; kt += KT1) {
        __syncthreads();
        // stage W[:, kt:kt+64] as tf32 into Wsh[n][k]
        #pragma unroll
        for (int it = 0; it < 8; it++) {
            const int e  = tid + it * 256;        // 0..2047
            const int n  = e >> 4;                // 0..127
            const int c4 = e & 15;                // float4 idx in k-tile
            float4 wv = __ldg(((const float4*)W) + n * (2 * DD / 4) + (kt >> 2) + c4);
            uint32_t* ws = (uint32_t*)(Wsh + n * WPAD + c4 * 4);
            ws[0] = f2tf32(wv.x); ws[1] = f2tf32(wv.y);
            ws[2] = f2tf32(wv.z); ws[3] = f2tf32(wv.w);
        }
        __syncthreads();

        #pragma unroll
        for (int k0 = 0; k0 < KT1; k0 += 8) {
            const uint32_t* ap = (const uint32_t*)(comb + (mbase + g) * CPAD + kt + k0 + tig);
            uint32_t a0 = ap[0];
            uint32_t a1 = ap[8 * CPAD];
            uint32_t a2 = ap[4];
            uint32_t a3 = ap[8 * CPAD + 4];
            #pragma unroll
            for (int nt = 0; nt < 8; nt++) {
                const uint32_t* bp = (const uint32_t*)(Wsh + (nbase + nt * 8 + g) * WPAD + k0 + tig);
                uint32_t bb0 = bp[0];
                uint32_t bb1 = bp[4];
                mma_tf32(acc[nt][0], acc[nt][1], acc[nt][2], acc[nt][3],
                         a0, a1, a2, a3, bb0, bb1);
            }
        }
    }

    // ---------- Epilogue: ReLU + store ----------
    #pragma unroll
    for (int nt = 0; nt < 8; nt++) {
        const int row = b0 + mbase + g;
        const int col = nbase + nt * 8 + 2 * tig;
        float2 v0 = make_float2(fmaxf(acc[nt][0], 0.f), fmaxf(acc[nt][1], 0.f));
        float2 v1 = make_float2(fmaxf(acc[nt][2], 0.f), fmaxf(acc[nt][3], 0.f));
        *(float2*)(out + (long long)row * DD + col)       = v0;
        *(float2*)(out + (long long)(row + 8) * DD + col) = v1;
    }
}

// ---------------------------------------------------------------------------
// Layer-2 kernel: fp32 FFMA, BM=16 (small-B occupancy)
// ---------------------------------------------------------------------------
#define BM2 16
#define KT2 64

__global__ __launch_bounds__(256, 4)
void sage_l2_fp32(const float* __restrict__ table,   // [B1][128] = h1
                  const float* __restrict__ W,       // [128][256]
                  const int*   __restrict__ nodes,
                  const int*   __restrict__ neigh,
                  float*       __restrict__ out,
                  int B)
{
    extern __shared__ __align__(16) float smem[];
    float* comb = smem;                      // [BM2][256]
    float* Wsh  = comb + BM2 * 2 * DD;       // [128][WPAD]

    const int tid  = threadIdx.x;
    const int warp = tid >> 5;
    const int lane = tid & 31;
    const int b0   = blockIdx.x * BM2;

    #pragma unroll
    for (int r = warp; r < BM2; r += 8) {
        const int row = b0 + r;
        const int node = nodes[row];
        float4 v = __ldg(((const float4*)table) + (long long)node * 32 + lane);
        ((float4*)(comb + r * 2 * DD))[lane] = v;
        float4 acc = make_float4(0.f, 0.f, 0.f, 0.f);
        #pragma unroll
        for (int k = 0; k < KN; k++) {
            const int idx = neigh[row * KN + k];
            float4 u = __ldg(((const float4*)table) + (long long)idx * 32 + lane);
            acc.x += u.x; acc.y += u.y; acc.z += u.z; acc.w += u.w;
        }
        const float s = 1.0f / (float)KN;
        acc.x *= s; acc.y *= s; acc.z *= s; acc.w *= s;
        ((float4*)(comb + r * 2 * DD))[32 + lane] = acc;
    }

    const int tx = tid & 15;     // 8 cols: tx + 16j
    const int ty = tid >> 4;     // 1 row

    float acc[8];
    #pragma unroll
    for (int j = 0; j < 8; j++) acc[j] = 0.f;

    for (int kt = 0; kt < 2 * DD; kt += KT2) {
        __syncthreads();
        #pragma unroll
        for (int r8 = 0; r8 < 8; r8++) {
            const int rw = (tid >> 4) + r8 * 16;
            const int c4 = (tid & 15);
            float4 wv = __ldg(((const float4*)W) + rw * (2 * DD / 4) + (kt >> 2) + c4);
            *((float4*)(Wsh + rw * WPAD + c4 * 4)) = wv;
        }
        __syncthreads();

        #pragma unroll
        for (int k0 = 0; k0 < KT2; k0 += 4) {
            float4 a4 = *((const float4*)(comb + ty * 2 * DD + kt + k0));
            #pragma unroll
            for (int j = 0; j < 8; j++) {
                float4 b4 = *((const float4*)(Wsh + (tx + 16 * j) * WPAD + k0));
                acc[j] += a4.x * b4.x + a4.y * b4.y + a4.z * b4.z + a4.w * b4.w;
            }
        }
    }

    const int row = b0 + ty;
    #pragma unroll
    for (int j = 0; j < 8; j++)
        out[(long long)row * DD + tx + 16 * j] = fmaxf(acc[j], 0.f);
}

extern "C" void kernel_launch(void* const* d_in, const int* in_sizes, int n_in,
                              void* d_out, int out_size)
{
    const float* raw    = (const float*)d_in[0];
    const float* W1     = (const float*)d_in[1];
    const float* W2     = (const float*)d_in[2];
    const int*   nodes1 = (const int*)  d_in[3];
    const int*   neigh1 = (const int*)  d_in[4];
    const int*   nodes2 = (const int*)  d_in[5];
    const int*   neigh2 = (const int*)  d_in[6];
    float*       out    = (float*)d_out;

    float* h1 = nullptr;
    cudaGetSymbolAddress((void**)&h1, g_h1);

    const int smem1 = (BM1 * CPAD + DD * WPAD) * (int)sizeof(float);   // 101,376 B
    const int smem2 = (BM2 * 2 * DD + DD * WPAD) * (int)sizeof(float); // 51,200 B

    static bool attr_done = false;
    if (!attr_done) {
        cudaFuncSetAttribute(sage_l1_tf32,
                             cudaFuncAttributeMaxDynamicSharedMemorySize, smem1);
        cudaFuncSetAttribute(sage_l2_fp32,
                             cudaFuncAttributeMaxDynamicSharedMemorySize, smem2);
        attr_done = true;
    }

    sage_l1_tf32<<<B1_SZ / BM1, 256, smem1>>>(raw, W1, nodes1, neigh1, h1, B1_SZ);
    sage_l2_fp32<<<B2_SZ / BM2, 256, smem2>>>(h1,  W2, nodes2, neigh2, out, B2_SZ);
}